// round 17
// baseline (speedup 1.0000x reference)
#include <cuda_runtime.h>
#include <cstdint>

// ---------------- problem constants ----------------
#define T      256
#define Hd     1024
#define E      256
#define Id     256
#define TOPK   8
#define NGROUP 8
#define GSIZE  32          // E / NGROUP
#define TOPKG  4
#define SCALE  2.5f

#define TC     16          // tokens per chunk per expert CTA
#define NP     8           // token pairs (TC/2)
#define XPF    16          // floats per smem row (u64/128b aligned; reads are broadcast)
#define XPU    8           // u64 per smem row
#define SH     4           // h-rows per gate/up stage
#define SI     8           // i-rows per down stage
#define DEPTH  3           // cp.async pipeline depth (warp-private)
#define STG_F  256         // floats per stage buffer (8 rows x 32 lanes)

typedef unsigned long long u64;

// ---------------- device scratch (no allocations allowed) ----------------
__device__ float g_logits[T * E];
__device__ int   g_cnt[E];
__device__ int   g_tok[E * T];
__device__ float g_wt[E * T];

// ---------------- packed f32x2 helpers ----------------
__device__ __forceinline__ u64 ffma2(u64 a, u64 b, u64 c) {
    u64 d;
    asm("fma.rn.f32x2 %0, %1, %2, %3;" : "=l"(d) : "l"(a), "l"(b), "l"(c));
    return d;
}
__device__ __forceinline__ u64 dup2(float v) {
    u64 d;
    asm("mov.b64 %0, {%1, %1};" : "=l"(d) : "f"(v));
    return d;
}
__device__ __forceinline__ float2 unpack2(u64 v) {
    float2 f;
    asm("mov.b64 {%0, %1}, %2;" : "=f"(f.x), "=f"(f.y) : "l"(v));
    return f;
}
__device__ __forceinline__ uint32_t smem_u32(const void* p) {
    uint32_t a;
    asm("{ .reg .u64 t; cvta.to.shared.u64 t, %1; cvt.u32.u64 %0, t; }"
        : "=r"(a) : "l"(p));
    return a;
}
__device__ __forceinline__ void cp16(uint32_t dst, const float* src) {
    asm volatile("cp.async.cg.shared.global [%0], [%1], 16;" :: "r"(dst), "l"(src));
}
#define CP_COMMIT() asm volatile("cp.async.commit_group;" ::: "memory")
#define CP_WAIT1()  asm volatile("cp.async.wait_group 1;"  ::: "memory")
#define CP_WAIT0()  asm volatile("cp.async.wait_group 0;"  ::: "memory")
// load 2 consecutive u64 (LDS.128)
__device__ __forceinline__ void lds2(const u64* p, u64& a, u64& b) {
    asm("ld.shared.v2.u64 {%0, %1}, [%2];" : "=l"(a), "=l"(b) : "l"(p));
}

// ---------------- kernel 0: zero output + expert counters ----------------
__global__ void zero_kernel(float* __restrict__ y) {
    int i = blockIdx.x * 256 + threadIdx.x;
    if (i < T * Hd) y[i] = 0.0f;
    if (i < E) g_cnt[i] = 0;
}

// ---------------- kernel 1: gate logits, 32x32 tiles (64 CTAs) ----------------
__global__ __launch_bounds__(256) void gate_gemm(const float* __restrict__ X,
                                                 const float* __restrict__ W) {
    __shared__ float Xs[32][33];   // [k][t]
    __shared__ float Ws[32][33];   // [k][e]
    int t0 = blockIdx.x * 32;
    int e0 = blockIdx.y * 32;
    int tid = threadIdx.x;
    int tx = tid & 7;              // expert quad
    int ty = tid >> 3;             // token
    float acc[4] = {0.f, 0.f, 0.f, 0.f};

    for (int k0 = 0; k0 < Hd; k0 += 32) {
#pragma unroll
        for (int l = 0; l < 4; l++) {
            int idx = tid + l * 256;
            int r = idx >> 5;      // 0..31
            int kk = idx & 31;
            Xs[kk][r] = X[(size_t)(t0 + r) * Hd + k0 + kk];
            Ws[kk][r] = W[(size_t)(e0 + r) * Hd + k0 + kk];
        }
        __syncthreads();
#pragma unroll
        for (int kk = 0; kk < 32; kk++) {
            float a = Xs[kk][ty];
#pragma unroll
            for (int q = 0; q < 4; q++)
                acc[q] = fmaf(a, Ws[kk][tx * 4 + q], acc[q]);
        }
        __syncthreads();
    }
#pragma unroll
    for (int q = 0; q < 4; q++)
        g_logits[(t0 + ty) * E + e0 + tx * 4 + q] = acc[q];
}

// ---------------- kernel 2: per-token routing (noaux_tc) ----------------
__global__ void route_kernel(const float* __restrict__ e_bias) {
    int t = blockIdx.x * blockDim.x + threadIdx.x;
    if (t >= T) return;
    const float* lrow = g_logits + t * E;

    float sc[E];
#pragma unroll 4
    for (int e = 0; e < E; e++) {
        float s = 1.0f / (1.0f + expf(-lrow[e]));
        sc[e] = s + e_bias[e];
    }

    float gs[NGROUP];
    for (int g = 0; g < NGROUP; g++) {
        float m1 = -1e30f, m2 = -1e30f;
        for (int j = 0; j < GSIZE; j++) {
            float v = sc[g * GSIZE + j];
            if (v > m1) { m2 = m1; m1 = v; }
            else if (v > m2) { m2 = v; }
        }
        gs[g] = m1 + m2;
    }

    unsigned gmask = 0;
    for (int r = 0; r < TOPKG; r++) {
        float best = -1e30f; int bi = 0;
        for (int g = 0; g < NGROUP; g++)
            if (!((gmask >> g) & 1u) && gs[g] > best) { best = gs[g]; bi = g; }
        gmask |= 1u << bi;
    }

    float bv[TOPK]; int bix[TOPK];
#pragma unroll
    for (int r = 0; r < TOPK; r++) { bv[r] = -1e30f; bix[r] = 0; }
    for (int e = 0; e < E; e++) {
        if (!((gmask >> (e >> 5)) & 1u)) continue;
        float v = sc[e];
        if (v <= bv[TOPK - 1]) continue;
        int pos = TOPK - 1;
        while (pos > 0 && bv[pos - 1] < v) {
            bv[pos] = bv[pos - 1]; bix[pos] = bix[pos - 1]; pos--;
        }
        bv[pos] = v; bix[pos] = e;
    }

    float wv[TOPK]; float wsum = 0.0f;
#pragma unroll
    for (int r = 0; r < TOPK; r++) {
        wv[r] = 1.0f / (1.0f + expf(-lrow[bix[r]]));
        wsum += wv[r];
    }
    float inv = SCALE / (wsum + 1e-20f);
#pragma unroll
    for (int r = 0; r < TOPK; r++) {
        int e = bix[r];
        int pos = atomicAdd(&g_cnt[e], 1);
        g_tok[e * T + pos] = t;
        g_wt[e * T + pos]  = wv[r] * inv;
    }
}

// ---------------- kernel 3: expert MLPs (routed + shared) ----------------
// Weights streamed through warp-private cp.async double(-triple)-buffered smem
// stages: LDGSTS keeps >=2 full stages (2KB) in flight per warp with zero
// register cost, hiding the ~577cyc DRAM latency that stalled the register-
// prefetch version at issue=35%.
__global__ __launch_bounds__(256, 2) void expert_kernel(
    const float* __restrict__ x,
    const float* __restrict__ w_gate, const float* __restrict__ w_up,
    const float* __restrict__ w_down,
    const float* __restrict__ sw_gate, const float* __restrict__ sw_up,
    const float* __restrict__ sw_down,
    float* __restrict__ y)
{
    extern __shared__ float smem[];
    float* xs  = smem;                          // Hd * XPF floats (64KB)
    float* as  = smem + Hd * XPF;               // Id * XPF floats (16KB)
    float* wst = smem + Hd * XPF + Id * XPF;    // 8 warps * DEPTH * STG_F (24KB)
    const u64* xsu = (const u64*)xs;
    const u64* asu = (const u64*)as;
    __shared__ int   s_tok[TC];
    __shared__ float s_w[TC];

    const int tid  = threadIdx.x;
    const int lane = tid & 31;
    const int warp = tid >> 5;
    float* mywst = wst + warp * DEPTH * STG_F;
    const uint32_t mywst_a = smem_u32(mywst);

    const int e = blockIdx.x;
    const bool sh = (e >= E);

    const float *Wg, *Wu, *Wd;
    int nt, base = 0;
    if (sh) {
        Wg = sw_gate; Wu = sw_up; Wd = sw_down;
        nt = TC; base = (e - E) * TC;
    } else {
        size_t off = (size_t)e * Hd * Id;
        Wg = w_gate + off; Wu = w_up + off; Wd = w_down + off;
        nt = g_cnt[e];
    }
    const int nchunk = (nt + TC - 1) / TC;

    // per-thread fill assignment: 2 x 16B per stage
    const int row0 = lane >> 3;              // k=0: rows 0..3
    const int row1 = (lane >> 3) + 4;        // k=1: rows 4..7
    const int ch4  = (lane & 7) * 4;         // 16B chunk within 128B row

    for (int ch = 0; ch < nchunk; ch++) {
        if (tid < TC) {
            int slot = ch * TC + tid;
            if (sh)             { s_tok[tid] = base + tid;          s_w[tid] = 1.0f; }
            else if (slot < nt) { s_tok[tid] = g_tok[e * T + slot]; s_w[tid] = g_wt[e * T + slot]; }
            else                { s_tok[tid] = 0;                   s_w[tid] = 0.0f; }
        }
        __syncthreads();

        // gather X rows (coalesced LDG)
        for (int idx = tid; idx < TC * Hd; idx += 256) {
            int t = idx >> 10;          // / Hd
            int h = idx & (Hd - 1);
            xs[h * XPF + t] = x[(size_t)s_tok[t] * Hd + h];
        }
        __syncthreads();

        // ================= gate + up projections =================
        // thread owns column i = tid of I; warp streams its 32-col weight slab
        {
            const float* gsrc = Wg + warp * 32;   // row stride Id
            const float* usrc = Wu + warp * 32;

            auto fill_gu = [&](int s) {
                uint32_t dbase = mywst_a + ((s % DEPTH) * STG_F) * 4;
                int h0 = s * SH;
                // rows: even=gate, odd=up; row = 2*j + gu
                {   int r = row0; int j = r >> 1;
                    const float* src = ((r & 1) ? usrc : gsrc) + (h0 + j) * Id + ch4;
                    cp16(dbase + (r * 32 + ch4) * 4, src); }
                {   int r = row1; int j = r >> 1;
                    const float* src = ((r & 1) ? usrc : gsrc) + (h0 + j) * Id + ch4;
                    cp16(dbase + (r * 32 + ch4) * 4, src); }
            };

            u64 a1[NP], a3[NP];
#pragma unroll
            for (int p = 0; p < NP; p++) { a1[p] = 0ull; a3[p] = 0ull; }

            fill_gu(0); CP_COMMIT();
            fill_gu(1); CP_COMMIT();
            const int NST = Hd / SH;   // 256
            for (int s = 0; s < NST; s++) {
                CP_WAIT1();
                __syncwarp();
                const float* buf = mywst + (s % DEPTH) * STG_F;
#pragma unroll
                for (int j = 0; j < SH; j++) {
                    u64 g2 = dup2(buf[(2 * j) * 32 + lane]);
                    u64 u2 = dup2(buf[(2 * j + 1) * 32 + lane]);
                    const u64* xr = xsu + (s * SH + j) * XPU;
#pragma unroll
                    for (int q = 0; q < NP / 2; q++) {
                        u64 x0, x1;
                        lds2(xr + 2 * q, x0, x1);
                        a1[2 * q]     = ffma2(x0, g2, a1[2 * q]);
                        a3[2 * q]     = ffma2(x0, u2, a3[2 * q]);
                        a1[2 * q + 1] = ffma2(x1, g2, a1[2 * q + 1]);
                        a3[2 * q + 1] = ffma2(x1, u2, a3[2 * q + 1]);
                    }
                }
                if (s + 2 < NST) fill_gu(s + 2);
                CP_COMMIT();
            }
            CP_WAIT0();

            // activation: A = w_t * silu(h1) * h3  (padded slots have w=0)
            const int i = tid;
#pragma unroll
            for (int p = 0; p < NP; p++) {
                float2 h1 = unpack2(a1[p]);
                float2 h3 = unpack2(a3[p]);
                float ax = s_w[2 * p]     * (h1.x / (1.0f + expf(-h1.x))) * h3.x;
                float ay = s_w[2 * p + 1] * (h1.y / (1.0f + expf(-h1.y))) * h3.y;
                as[i * XPF + 2 * p]     = ax;
                as[i * XPF + 2 * p + 1] = ay;
            }
        }
        __syncthreads();

        // ================= down projection: 4 col chunks of 256 =================
        for (int c = 0; c < Hd / Id; c++) {
            const float* dsrc = Wd + c * 256 + warp * 32;   // row stride Hd

            auto fill_d = [&](int s) {
                uint32_t dbase = mywst_a + ((s % DEPTH) * STG_F) * 4;
                int i0 = s * SI;
                cp16(dbase + (row0 * 32 + ch4) * 4, dsrc + (size_t)(i0 + row0) * Hd + ch4);
                cp16(dbase + (row1 * 32 + ch4) * 4, dsrc + (size_t)(i0 + row1) * Hd + ch4);
            };

            u64 acc[NP];
#pragma unroll
            for (int p = 0; p < NP; p++) acc[p] = 0ull;

            fill_d(0); CP_COMMIT();
            fill_d(1); CP_COMMIT();
            const int NSD = Id / SI;   // 32
            for (int s = 0; s < NSD; s++) {
                CP_WAIT1();
                __syncwarp();
                const float* buf = mywst + (s % DEPTH) * STG_F;
#pragma unroll
                for (int r = 0; r < SI; r++) {
                    u64 d2 = dup2(buf[r * 32 + lane]);
                    const u64* ar = asu + (s * SI + r) * XPU;
#pragma unroll
                    for (int q = 0; q < NP / 2; q++) {
                        u64 b0, b1;
                        lds2(ar + 2 * q, b0, b1);
                        acc[2 * q]     = ffma2(b0, d2, acc[2 * q]);
                        acc[2 * q + 1] = ffma2(b1, d2, acc[2 * q + 1]);
                    }
                }
                if (s + 2 < NSD) fill_d(s + 2);
                CP_COMMIT();
            }
            CP_WAIT0();

            const int col = c * 256 + tid;
#pragma unroll
            for (int p = 0; p < NP; p++) {
                float2 v = unpack2(acc[p]);
                if (s_w[2 * p] != 0.0f)
                    atomicAdd(&y[(size_t)s_tok[2 * p] * Hd + col], v.x);
                if (s_w[2 * p + 1] != 0.0f)
                    atomicAdd(&y[(size_t)s_tok[2 * p + 1] * Hd + col], v.y);
            }
        }
        __syncthreads();   // before next chunk overwrites xs/as/stages
    }
}

// ---------------- launch ----------------
extern "C" void kernel_launch(void* const* d_in, const int* in_sizes, int n_in,
                              void* d_out, int out_size) {
    const float* x       = (const float*)d_in[0];   // [1,1,T,H]
    const float* gate_w  = (const float*)d_in[1];   // [E,H]
    const float* e_bias  = (const float*)d_in[2];   // [E]
    const float* w_gate  = (const float*)d_in[3];   // [E,H,I]
    const float* w_up    = (const float*)d_in[4];   // [E,H,I]
    const float* w_down  = (const float*)d_in[5];   // [E,I,H]
    const float* sw_gate = (const float*)d_in[6];   // [H,I]
    const float* sw_up   = (const float*)d_in[7];   // [H,I]
    const float* sw_down = (const float*)d_in[8];   // [I,H]
    float* y = (float*)d_out;                       // [T*H] fp32

    const int SMEM_EXPERT = (Hd * XPF + Id * XPF + 8 * DEPTH * STG_F) * (int)sizeof(float); // 106496
    cudaFuncSetAttribute(expert_kernel,
                         cudaFuncAttributeMaxDynamicSharedMemorySize, SMEM_EXPERT);

    zero_kernel<<<(T * Hd + 255) / 256, 256>>>(y);
    gate_gemm<<<dim3(T / 32, E / 32), 256>>>(x, gate_w);
    route_kernel<<<(T + 31) / 32, 32>>>(e_bias);
    expert_kernel<<<E + T / TC, 256, SMEM_EXPERT>>>(
        x, w_gate, w_up, w_down, sw_gate, sw_up, sw_down, y);
}